// round 1
// baseline (speedup 1.0000x reference)
#include <cuda_runtime.h>
#include <math.h>

#define TOK   16384      // B*S = 4*4096
#define DIN   2048
#define HIDN  256
#define NHEAD 16
#define HDIM  128
#define KSEL  4
#define OUTW  (KSEL*HDIM)   // 512

// ---- device scratch (no allocations allowed) ----
__device__ float g_z[TOK * HIDN];        // router logits pre-norm [16384,256] (16MB)
__device__ float g_prob[TOK * KSEL];     // gate prob per (token, slot)
__device__ int   g_list[NHEAD * TOK];    // per-head token*4+slot lists
__device__ int   g_cnt[NHEAD];           // per-head counts
__device__ float g_cnorm[NHEAD * HIDN];  // normalized centroids

// ============================================================
// Kernel 0: zero counters + normalize centroids
// ============================================================
__global__ void prep_kernel(const float* __restrict__ cent) {
    int tid = threadIdx.x;
    if (tid < NHEAD) g_cnt[tid] = 0;
    int w = tid >> 5, lane = tid & 31;
    for (int n = w; n < NHEAD; n += 8) {
        float s = 0.f;
        for (int i = lane; i < HIDN; i += 32) {
            float v = cent[n * HIDN + i];
            s += v * v;
        }
        #pragma unroll
        for (int o = 16; o; o >>= 1) s += __shfl_xor_sync(0xffffffffu, s, o);
        float inv = 1.0f / fmaxf(sqrtf(s), 1e-12f);
        for (int i = lane; i < HIDN; i += 32)
            g_cnorm[n * HIDN + i] = cent[n * HIDN + i] * inv;
    }
}

// ============================================================
// Kernel 1: router GEMM  g_z[M,N] = X[M,K] * Wr[N,K]^T
// 128x128 tile, BK=16, 256 threads, 8x8 per thread
// ============================================================
__global__ __launch_bounds__(256, 2) void gemm_router(
    const float* __restrict__ X, const float* __restrict__ Wr) {
    __shared__ float As[16][128];
    __shared__ float Bs[16][128];
    int tid = threadIdx.x;
    int m0 = blockIdx.y * 128;
    int n0 = blockIdx.x * 128;
    int tm0 = (tid >> 4) << 3;
    int tn0 = (tid & 15) << 3;

    float acc[8][8];
    #pragma unroll
    for (int i = 0; i < 8; i++)
        #pragma unroll
        for (int j = 0; j < 8; j++) acc[i][j] = 0.f;

    for (int k0 = 0; k0 < DIN; k0 += 16) {
        #pragma unroll
        for (int it = 0; it < 2; it++) {
            int id = tid + it * 256;
            int row = id >> 2, c4 = id & 3;
            float4 av = *(const float4*)&X[(size_t)(m0 + row) * DIN + k0 + c4 * 4];
            As[c4 * 4 + 0][row] = av.x;
            As[c4 * 4 + 1][row] = av.y;
            As[c4 * 4 + 2][row] = av.z;
            As[c4 * 4 + 3][row] = av.w;
            float4 bv = *(const float4*)&Wr[(size_t)(n0 + row) * DIN + k0 + c4 * 4];
            Bs[c4 * 4 + 0][row] = bv.x;
            Bs[c4 * 4 + 1][row] = bv.y;
            Bs[c4 * 4 + 2][row] = bv.z;
            Bs[c4 * 4 + 3][row] = bv.w;
        }
        __syncthreads();
        #pragma unroll
        for (int k = 0; k < 16; k++) {
            float4 a0 = *(const float4*)&As[k][tm0];
            float4 a1 = *(const float4*)&As[k][tm0 + 4];
            float4 b0 = *(const float4*)&Bs[k][tn0];
            float4 b1 = *(const float4*)&Bs[k][tn0 + 4];
            float a[8] = {a0.x, a0.y, a0.z, a0.w, a1.x, a1.y, a1.z, a1.w};
            float b[8] = {b0.x, b0.y, b0.z, b0.w, b1.x, b1.y, b1.z, b1.w};
            #pragma unroll
            for (int i = 0; i < 8; i++)
                #pragma unroll
                for (int j = 0; j < 8; j++) acc[i][j] += a[i] * b[j];
        }
        __syncthreads();
    }
    #pragma unroll
    for (int i = 0; i < 8; i++) {
        #pragma unroll
        for (int j = 0; j < 8; j++)
            g_z[(size_t)(m0 + tm0 + i) * HIDN + n0 + tn0 + j] = acc[i][j];
    }
}

// ============================================================
// Kernel 2: per-token routing: l2norm(z) . c_norm, softmax, top-4,
//           dispatch into per-head lists
// ============================================================
__global__ void route_kernel(const float* __restrict__ temp) {
    int t = blockIdx.x;
    int tid = threadIdx.x;
    int lane = tid & 31, w = tid >> 5;
    __shared__ float zs[256];
    __shared__ float red[8];
    __shared__ float slog[16];

    float z = g_z[(size_t)t * HIDN + tid];
    zs[tid] = z;
    float s = z * z;
    #pragma unroll
    for (int o = 16; o; o >>= 1) s += __shfl_xor_sync(0xffffffffu, s, o);
    if (lane == 0) red[w] = s;
    __syncthreads();
    float tot = 0.f;
    #pragma unroll
    for (int i = 0; i < 8; i++) tot += red[i];
    float inv = 1.0f / fmaxf(sqrtf(tot), 1e-12f);

    // 8 warps, 2 centroids each
    for (int n = w; n < NHEAD; n += 8) {
        float p = 0.f;
        for (int i = lane; i < HIDN; i += 32) p += zs[i] * g_cnorm[n * HIDN + i];
        #pragma unroll
        for (int o = 16; o; o >>= 1) p += __shfl_xor_sync(0xffffffffu, p, o);
        if (lane == 0) slog[n] = p;
    }
    __syncthreads();

    if (tid == 0) {
        float sc = inv * 0.0625f * expf(temp[0]);  // 1/sqrt(256) = 1/16
        float lg[16];
        float mx = -1e30f;
        #pragma unroll
        for (int n = 0; n < NHEAD; n++) {
            lg[n] = slog[n] * sc;
            mx = fmaxf(mx, lg[n]);
        }
        float sum = 0.f;
        #pragma unroll
        for (int n = 0; n < NHEAD; n++) {
            lg[n] = expf(lg[n] - mx);
            sum += lg[n];
        }
        float isum = 1.0f / sum;
        bool used[16];
        #pragma unroll
        for (int n = 0; n < NHEAD; n++) used[n] = false;
        for (int k = 0; k < KSEL; k++) {
            int bi = 0;
            float bv = -1e30f;
            #pragma unroll
            for (int n = 0; n < NHEAD; n++) {
                if (!used[n] && lg[n] > bv) { bv = lg[n]; bi = n; }
            }
            used[bi] = true;
            g_prob[t * KSEL + k] = bv * isum;
            int pos = atomicAdd(&g_cnt[bi], 1);
            g_list[bi * TOK + pos] = (t << 2) | k;
        }
    }
}

// ============================================================
// Kernel 3: grouped expert GEMM with gather/scatter.
// grid = (TOK/128, NHEAD). Per head h: C[n_h,128] = Xg[n_h,2048] * Wh^T
// epilogue: out[t, slot*128+n] = (acc + bias) * prob
// ============================================================
__global__ __launch_bounds__(256, 2) void gemm_expert(
    const float* __restrict__ X, const float* __restrict__ W,
    const float* __restrict__ bias, float* __restrict__ out) {
    int h = blockIdx.y;
    int cnt = g_cnt[h];
    int base = blockIdx.x * 128;
    if (base >= cnt) return;

    __shared__ float As[16][128];
    __shared__ float Bs[16][128];
    __shared__ int   s_ent[128];
    __shared__ float s_prob[128];

    int tid = threadIdx.x;
    if (tid < 128) {
        int r = base + tid;
        int rr = (r < cnt) ? r : (cnt - 1);
        int ent = g_list[h * TOK + rr];
        s_ent[tid] = ent;
        s_prob[tid] = g_prob[ent];  // ent == t*4+slot is exactly the prob index
    }
    __syncthreads();

    int tm0 = (tid >> 4) << 3;
    int tn0 = (tid & 15) << 3;
    float acc[8][8];
    #pragma unroll
    for (int i = 0; i < 8; i++)
        #pragma unroll
        for (int j = 0; j < 8; j++) acc[i][j] = 0.f;

    const float* Wh = W + (size_t)h * HDIM * DIN;

    for (int k0 = 0; k0 < DIN; k0 += 16) {
        #pragma unroll
        for (int it = 0; it < 2; it++) {
            int id = tid + it * 256;
            int row = id >> 2, c4 = id & 3;
            int tok = s_ent[row] >> 2;
            float4 av = *(const float4*)&X[(size_t)tok * DIN + k0 + c4 * 4];
            As[c4 * 4 + 0][row] = av.x;
            As[c4 * 4 + 1][row] = av.y;
            As[c4 * 4 + 2][row] = av.z;
            As[c4 * 4 + 3][row] = av.w;
            float4 bv = *(const float4*)&Wh[(size_t)row * DIN + k0 + c4 * 4];
            Bs[c4 * 4 + 0][row] = bv.x;
            Bs[c4 * 4 + 1][row] = bv.y;
            Bs[c4 * 4 + 2][row] = bv.z;
            Bs[c4 * 4 + 3][row] = bv.w;
        }
        __syncthreads();
        #pragma unroll
        for (int k = 0; k < 16; k++) {
            float4 a0 = *(const float4*)&As[k][tm0];
            float4 a1 = *(const float4*)&As[k][tm0 + 4];
            float4 b0 = *(const float4*)&Bs[k][tn0];
            float4 b1 = *(const float4*)&Bs[k][tn0 + 4];
            float a[8] = {a0.x, a0.y, a0.z, a0.w, a1.x, a1.y, a1.z, a1.w};
            float b[8] = {b0.x, b0.y, b0.z, b0.w, b1.x, b1.y, b1.z, b1.w};
            #pragma unroll
            for (int i = 0; i < 8; i++)
                #pragma unroll
                for (int j = 0; j < 8; j++) acc[i][j] += a[i] * b[j];
        }
        __syncthreads();
    }

    #pragma unroll
    for (int i = 0; i < 8; i++) {
        int r = tm0 + i;
        if (base + r < cnt) {
            int ent = s_ent[r];
            int t = ent >> 2;
            int slot = ent & 3;
            float p = s_prob[r];
            float* op = out + (size_t)t * OUTW + slot * HDIM + tn0;
            #pragma unroll
            for (int j = 0; j < 8; j++)
                op[j] = (acc[i][j] + bias[h * HDIM + tn0 + j]) * p;
        }
    }
}

// ============================================================
extern "C" void kernel_launch(void* const* d_in, const int* in_sizes, int n_in,
                              void* d_out, int out_size) {
    const float* x    = (const float*)d_in[0];  // [4,4096,2048]
    const float* rw   = (const float*)d_in[1];  // [256,2048]
    const float* cent = (const float*)d_in[2];  // [16,256]
    const float* temp = (const float*)d_in[3];  // [1]
    const float* w    = (const float*)d_in[4];  // [2048,2048]
    const float* b    = (const float*)d_in[5];  // [2048]
    float* out = (float*)d_out;                 // [4,4096,512]

    prep_kernel<<<1, 256>>>(cent);
    gemm_router<<<dim3(HIDN / 128, TOK / 128), 256>>>(x, rw);
    route_kernel<<<TOK, 256>>>(temp);
    gemm_expert<<<dim3(TOK / 128, NHEAD), 256>>>(x, w, b, out);
}

// round 3
// speedup vs baseline: 1.5405x; 1.5405x over previous
#include <cuda_runtime.h>
#include <math.h>

#define TOK   16384      // B*S = 4*4096
#define DIN   2048
#define HIDN  256
#define NHEAD 16
#define HDIM  128
#define KSEL  4
#define OUTW  (KSEL*HDIM)   // 512

// ---- device scratch (no allocations allowed) ----
__device__ float g_z[TOK * HIDN];        // router logits pre-norm [16384,256]
__device__ float g_prob[TOK * KSEL];     // gate prob per (token, slot)
__device__ int   g_list[NHEAD * TOK];    // per-head token*4+slot lists
__device__ int   g_cnt[NHEAD];           // per-head counts
__device__ float g_cnorm[NHEAD * HIDN];  // normalized centroids

// ---- tf32 helpers ----
__device__ __forceinline__ unsigned f2tf32(float x) {
    unsigned r;
    asm("cvt.rna.tf32.f32 %0, %1;" : "=r"(r) : "f"(x));
    return r;
}

__device__ __forceinline__ void mma_tf32(float* c, const unsigned* a, const unsigned* b) {
    asm volatile(
        "mma.sync.aligned.m16n8k8.row.col.f32.tf32.tf32.f32 "
        "{%0,%1,%2,%3}, {%4,%5,%6,%7}, {%8,%9}, {%0,%1,%2,%3};"
        : "+f"(c[0]), "+f"(c[1]), "+f"(c[2]), "+f"(c[3])
        : "r"(a[0]), "r"(a[1]), "r"(a[2]), "r"(a[3]), "r"(b[0]), "r"(b[1]));
}

// ============================================================
// Kernel 0: zero counters + normalize centroids
// ============================================================
__global__ void prep_kernel(const float* __restrict__ cent) {
    int tid = threadIdx.x;
    if (tid < NHEAD) g_cnt[tid] = 0;
    int w = tid >> 5, lane = tid & 31;
    for (int n = w; n < NHEAD; n += 8) {
        float s = 0.f;
        for (int i = lane; i < HIDN; i += 32) {
            float v = cent[n * HIDN + i];
            s += v * v;
        }
        #pragma unroll
        for (int o = 16; o; o >>= 1) s += __shfl_xor_sync(0xffffffffu, s, o);
        float inv = 1.0f / fmaxf(sqrtf(s), 1e-12f);
        for (int i = lane; i < HIDN; i += 32)
            g_cnorm[n * HIDN + i] = cent[n * HIDN + i] * inv;
    }
}

// ============================================================
// Kernel 1: router GEMM (fp32 SIMT, proven ranking-exact)
// g_z[M,N] = X[M,K] * Wr[N,K]^T
// 128x128 tile, BK=16, 256 threads, 8x8 per thread
// ============================================================
__global__ __launch_bounds__(256, 2) void gemm_router(
    const float* __restrict__ X, const float* __restrict__ Wr) {
    __shared__ float As[16][128];
    __shared__ float Bs[16][128];
    int tid = threadIdx.x;
    int m0 = blockIdx.y * 128;
    int n0 = blockIdx.x * 128;
    int tm0 = (tid >> 4) << 3;
    int tn0 = (tid & 15) << 3;

    float acc[8][8];
    #pragma unroll
    for (int i = 0; i < 8; i++)
        #pragma unroll
        for (int j = 0; j < 8; j++) acc[i][j] = 0.f;

    for (int k0 = 0; k0 < DIN; k0 += 16) {
        #pragma unroll
        for (int it = 0; it < 2; it++) {
            int id = tid + it * 256;
            int row = id >> 2, c4 = id & 3;
            float4 av = *(const float4*)&X[(size_t)(m0 + row) * DIN + k0 + c4 * 4];
            As[c4 * 4 + 0][row] = av.x;
            As[c4 * 4 + 1][row] = av.y;
            As[c4 * 4 + 2][row] = av.z;
            As[c4 * 4 + 3][row] = av.w;
            float4 bv = *(const float4*)&Wr[(size_t)(n0 + row) * DIN + k0 + c4 * 4];
            Bs[c4 * 4 + 0][row] = bv.x;
            Bs[c4 * 4 + 1][row] = bv.y;
            Bs[c4 * 4 + 2][row] = bv.z;
            Bs[c4 * 4 + 3][row] = bv.w;
        }
        __syncthreads();
        #pragma unroll
        for (int k = 0; k < 16; k++) {
            float4 a0 = *(const float4*)&As[k][tm0];
            float4 a1 = *(const float4*)&As[k][tm0 + 4];
            float4 b0 = *(const float4*)&Bs[k][tn0];
            float4 b1 = *(const float4*)&Bs[k][tn0 + 4];
            float a[8] = {a0.x, a0.y, a0.z, a0.w, a1.x, a1.y, a1.z, a1.w};
            float b[8] = {b0.x, b0.y, b0.z, b0.w, b1.x, b1.y, b1.z, b1.w};
            #pragma unroll
            for (int i = 0; i < 8; i++)
                #pragma unroll
                for (int j = 0; j < 8; j++) acc[i][j] += a[i] * b[j];
        }
        __syncthreads();
    }
    #pragma unroll
    for (int i = 0; i < 8; i++) {
        #pragma unroll
        for (int j = 0; j < 8; j++)
            g_z[(size_t)(m0 + tm0 + i) * HIDN + n0 + tn0 + j] = acc[i][j];
    }
}

// ============================================================
// Kernel 2: per-token routing: l2norm(z) . c_norm, softmax, top-4,
//           dispatch into per-head lists
// ============================================================
__global__ void route_kernel(const float* __restrict__ temp) {
    int t = blockIdx.x;
    int tid = threadIdx.x;
    int lane = tid & 31, w = tid >> 5;
    __shared__ float zs[256];
    __shared__ float red[8];
    __shared__ float slog[16];

    float z = g_z[(size_t)t * HIDN + tid];
    zs[tid] = z;
    float s = z * z;
    #pragma unroll
    for (int o = 16; o; o >>= 1) s += __shfl_xor_sync(0xffffffffu, s, o);
    if (lane == 0) red[w] = s;
    __syncthreads();
    float tot = 0.f;
    #pragma unroll
    for (int i = 0; i < 8; i++) tot += red[i];
    float inv = 1.0f / fmaxf(sqrtf(tot), 1e-12f);

    for (int n = w; n < NHEAD; n += 8) {
        float p = 0.f;
        for (int i = lane; i < HIDN; i += 32) p += zs[i] * g_cnorm[n * HIDN + i];
        #pragma unroll
        for (int o = 16; o; o >>= 1) p += __shfl_xor_sync(0xffffffffu, p, o);
        if (lane == 0) slog[n] = p;
    }
    __syncthreads();

    if (tid == 0) {
        float sc = inv * 0.0625f * expf(temp[0]);
        float lg[16];
        float mx = -1e30f;
        #pragma unroll
        for (int n = 0; n < NHEAD; n++) {
            lg[n] = slog[n] * sc;
            mx = fmaxf(mx, lg[n]);
        }
        float sum = 0.f;
        #pragma unroll
        for (int n = 0; n < NHEAD; n++) {
            lg[n] = expf(lg[n] - mx);
            sum += lg[n];
        }
        float isum = 1.0f / sum;
        bool used[16];
        #pragma unroll
        for (int n = 0; n < NHEAD; n++) used[n] = false;
        for (int k = 0; k < KSEL; k++) {
            int bi = 0;
            float bv = -1e30f;
            #pragma unroll
            for (int n = 0; n < NHEAD; n++) {
                if (!used[n] && lg[n] > bv) { bv = lg[n]; bi = n; }
            }
            used[bi] = true;
            g_prob[t * KSEL + k] = bv * isum;
            int pos = atomicAdd(&g_cnt[bi], 1);
            g_list[bi * TOK + pos] = (t << 2) | k;
        }
    }
}

// ============================================================
// Kernel 3: grouped expert GEMM (single-pass tf32 mma) + gather/scatter.
// grid = (TOK/128, NHEAD). Per head h: C[n_h,128] = Xg[n_h,2048] * Wh^T.
// Tile 128x128, BK=32, 8 warps (4m x 2n), warp tile 32x64.
// Epilogue: out[t, slot*128+n] = (acc + bias) * prob
// ============================================================
__global__ __launch_bounds__(256, 2) void gemm_expert_mma(
    const float* __restrict__ X, const float* __restrict__ W,
    const float* __restrict__ bias, float* __restrict__ out) {
    int h = blockIdx.y;
    int cnt = g_cnt[h];
    int base = blockIdx.x * 128;
    if (base >= cnt) return;

    __shared__ unsigned As[128][36];
    __shared__ unsigned Bs[128][36];
    __shared__ int   s_ent[128];
    __shared__ float s_prob[128];
    __shared__ float s_bias[128];

    int tid = threadIdx.x;
    if (tid < 128) {
        int r = base + tid;
        int rr = (r < cnt) ? r : (cnt - 1);
        int ent = g_list[h * TOK + rr];
        s_ent[tid] = ent;
        s_prob[tid] = g_prob[ent];
        s_bias[tid] = bias[h * HDIM + tid];
    }
    __syncthreads();

    int wid = tid >> 5, lane = tid & 31;
    int wm = wid >> 1, wn = wid & 1;
    int g = lane >> 2, t = lane & 3;

    float acc[2][8][4];
    #pragma unroll
    for (int i = 0; i < 2; i++)
        #pragma unroll
        for (int j = 0; j < 8; j++)
            #pragma unroll
            for (int q = 0; q < 4; q++) acc[i][j][q] = 0.f;

    const float* Wh = W + (size_t)h * HDIM * DIN;

    for (int k0 = 0; k0 < DIN; k0 += 32) {
        #pragma unroll
        for (int i = 0; i < 4; i++) {
            int idx = tid + i * 256;
            int row = idx >> 3, c4 = idx & 7;
            int tok = s_ent[row] >> 2;
            float4 v = *(const float4*)&X[(size_t)tok * DIN + k0 + c4 * 4];
            uint4 hv;
            hv.x = f2tf32(v.x); hv.y = f2tf32(v.y);
            hv.z = f2tf32(v.z); hv.w = f2tf32(v.w);
            *(uint4*)&As[row][c4 * 4] = hv;
            float4 w = *(const float4*)&Wh[(size_t)row * DIN + k0 + c4 * 4];
            hv.x = f2tf32(w.x); hv.y = f2tf32(w.y);
            hv.z = f2tf32(w.z); hv.w = f2tf32(w.w);
            *(uint4*)&Bs[row][c4 * 4] = hv;
        }
        __syncthreads();
        #pragma unroll
        for (int s = 0; s < 4; s++) {
            unsigned a[2][4], b[8][2];
            #pragma unroll
            for (int mt = 0; mt < 2; mt++) {
                int rm = wm * 32 + mt * 16 + g;
                int kc = s * 8 + t;
                a[mt][0] = As[rm][kc];     a[mt][1] = As[rm + 8][kc];
                a[mt][2] = As[rm][kc + 4]; a[mt][3] = As[rm + 8][kc + 4];
            }
            #pragma unroll
            for (int nt = 0; nt < 8; nt++) {
                int rn = wn * 64 + nt * 8 + g;
                int kc = s * 8 + t;
                b[nt][0] = Bs[rn][kc]; b[nt][1] = Bs[rn][kc + 4];
            }
            #pragma unroll
            for (int mt = 0; mt < 2; mt++)
                #pragma unroll
                for (int nt = 0; nt < 8; nt++)
                    mma_tf32(acc[mt][nt], a[mt], b[nt]);
        }
        __syncthreads();
    }

    #pragma unroll
    for (int mt = 0; mt < 2; mt++)
        #pragma unroll
        for (int half = 0; half < 2; half++) {
            int r = wm * 32 + mt * 16 + g + half * 8;
            if (base + r < cnt) {
                int ent = s_ent[r];
                int tok = ent >> 2, slot = ent & 3;
                float p = s_prob[r];
                float* op = out + (size_t)tok * OUTW + slot * HDIM;
                #pragma unroll
                for (int nt = 0; nt < 8; nt++) {
                    int col = wn * 64 + nt * 8 + 2 * t;
                    float2 v;
                    v.x = (acc[mt][nt][half * 2 + 0] + s_bias[col]) * p;
                    v.y = (acc[mt][nt][half * 2 + 1] + s_bias[col + 1]) * p;
                    *(float2*)&op[col] = v;
                }
            }
        }
}

// ============================================================
extern "C" void kernel_launch(void* const* d_in, const int* in_sizes, int n_in,
                              void* d_out, int out_size) {
    const float* x    = (const float*)d_in[0];  // [4,4096,2048]
    const float* rw   = (const float*)d_in[1];  // [256,2048]
    const float* cent = (const float*)d_in[2];  // [16,256]
    const float* temp = (const float*)d_in[3];  // [1]
    const float* w    = (const float*)d_in[4];  // [2048,2048]
    const float* b    = (const float*)d_in[5];  // [2048]
    float* out = (float*)d_out;                 // [4,4096,512]

    prep_kernel<<<1, 256>>>(cent);
    gemm_router<<<dim3(HIDN / 128, TOK / 128), 256>>>(x, rw);
    route_kernel<<<TOK, 256>>>(temp);
    gemm_expert_mma<<<dim3(TOK / 128, NHEAD), 256>>>(x, w, b, out);
}

// round 5
// speedup vs baseline: 1.7408x; 1.1300x over previous
#include <cuda_runtime.h>
#include <math.h>

#define TOK   16384      // B*S = 4*4096
#define DIN   2048
#define HIDN  256
#define NHEAD 16
#define HDIM  128
#define KSEL  4
#define OUTW  (KSEL*HDIM)   // 512

// ---- device scratch (no allocations allowed) ----
__device__ float g_z[TOK * HIDN];        // router logits pre-norm [16384,256]
__device__ float g_prob[TOK * KSEL];     // gate prob per (token, slot)
__device__ int   g_list[NHEAD * TOK];    // per-head token*4+slot lists
__device__ int   g_cnt[NHEAD];           // per-head counts
__device__ float g_cnorm[NHEAD * HIDN];  // normalized centroids

// ---- tf32 helpers ----
__device__ __forceinline__ unsigned f2tf32(float x) {
    unsigned r;
    asm("cvt.rna.tf32.f32 %0, %1;" : "=r"(r) : "f"(x));
    return r;
}
__device__ __forceinline__ void mma_tf32(float* c, const unsigned* a, const unsigned* b) {
    asm volatile(
        "mma.sync.aligned.m16n8k8.row.col.f32.tf32.tf32.f32 "
        "{%0,%1,%2,%3}, {%4,%5,%6,%7}, {%8,%9}, {%0,%1,%2,%3};"
        : "+f"(c[0]), "+f"(c[1]), "+f"(c[2]), "+f"(c[3])
        : "r"(a[0]), "r"(a[1]), "r"(a[2]), "r"(a[3]), "r"(b[0]), "r"(b[1]));
}

// ============================================================
// Kernel 0: zero counters + normalize centroids  (VERBATIM R3)
// ============================================================
__global__ void prep_kernel(const float* __restrict__ cent) {
    int tid = threadIdx.x;
    if (tid < NHEAD) g_cnt[tid] = 0;
    int w = tid >> 5, lane = tid & 31;
    for (int n = w; n < NHEAD; n += 8) {
        float s = 0.f;
        for (int i = lane; i < HIDN; i += 32) {
            float v = cent[n * HIDN + i];
            s += v * v;
        }
        #pragma unroll
        for (int o = 16; o; o >>= 1) s += __shfl_xor_sync(0xffffffffu, s, o);
        float inv = 1.0f / fmaxf(sqrtf(s), 1e-12f);
        for (int i = lane; i < HIDN; i += 32)
            g_cnorm[n * HIDN + i] = cent[n * HIDN + i] * inv;
    }
}

// ============================================================
// Kernel 1: router GEMM (fp32 SIMT, proven ranking-exact; VERBATIM R3)
// ============================================================
__global__ __launch_bounds__(256, 2) void gemm_router(
    const float* __restrict__ X, const float* __restrict__ Wr) {
    __shared__ float As[16][128];
    __shared__ float Bs[16][128];
    int tid = threadIdx.x;
    int m0 = blockIdx.y * 128;
    int n0 = blockIdx.x * 128;
    int tm0 = (tid >> 4) << 3;
    int tn0 = (tid & 15) << 3;

    float acc[8][8];
    #pragma unroll
    for (int i = 0; i < 8; i++)
        #pragma unroll
        for (int j = 0; j < 8; j++) acc[i][j] = 0.f;

    for (int k0 = 0; k0 < DIN; k0 += 16) {
        #pragma unroll
        for (int it = 0; it < 2; it++) {
            int id = tid + it * 256;
            int row = id >> 2, c4 = id & 3;
            float4 av = *(const float4*)&X[(size_t)(m0 + row) * DIN + k0 + c4 * 4];
            As[c4 * 4 + 0][row] = av.x;
            As[c4 * 4 + 1][row] = av.y;
            As[c4 * 4 + 2][row] = av.z;
            As[c4 * 4 + 3][row] = av.w;
            float4 bv = *(const float4*)&Wr[(size_t)(n0 + row) * DIN + k0 + c4 * 4];
            Bs[c4 * 4 + 0][row] = bv.x;
            Bs[c4 * 4 + 1][row] = bv.y;
            Bs[c4 * 4 + 2][row] = bv.z;
            Bs[c4 * 4 + 3][row] = bv.w;
        }
        __syncthreads();
        #pragma unroll
        for (int k = 0; k < 16; k++) {
            float4 a0 = *(const float4*)&As[k][tm0];
            float4 a1 = *(const float4*)&As[k][tm0 + 4];
            float4 b0 = *(const float4*)&Bs[k][tn0];
            float4 b1 = *(const float4*)&Bs[k][tn0 + 4];
            float a[8] = {a0.x, a0.y, a0.z, a0.w, a1.x, a1.y, a1.z, a1.w};
            float b[8] = {b0.x, b0.y, b0.z, b0.w, b1.x, b1.y, b1.z, b1.w};
            #pragma unroll
            for (int i = 0; i < 8; i++)
                #pragma unroll
                for (int j = 0; j < 8; j++) acc[i][j] += a[i] * b[j];
        }
        __syncthreads();
    }
    #pragma unroll
    for (int i = 0; i < 8; i++) {
        #pragma unroll
        for (int j = 0; j < 8; j++)
            g_z[(size_t)(m0 + tm0 + i) * HIDN + n0 + tn0 + j] = acc[i][j];
    }
}

// ============================================================
// Kernel 2: routing (VERBATIM R3)
// ============================================================
__global__ void route_kernel(const float* __restrict__ temp) {
    int t = blockIdx.x;
    int tid = threadIdx.x;
    int lane = tid & 31, w = tid >> 5;
    __shared__ float zs[256];
    __shared__ float red[8];
    __shared__ float slog[16];

    float z = g_z[(size_t)t * HIDN + tid];
    zs[tid] = z;
    float s = z * z;
    #pragma unroll
    for (int o = 16; o; o >>= 1) s += __shfl_xor_sync(0xffffffffu, s, o);
    if (lane == 0) red[w] = s;
    __syncthreads();
    float tot = 0.f;
    #pragma unroll
    for (int i = 0; i < 8; i++) tot += red[i];
    float inv = 1.0f / fmaxf(sqrtf(tot), 1e-12f);

    for (int n = w; n < NHEAD; n += 8) {
        float p = 0.f;
        for (int i = lane; i < HIDN; i += 32) p += zs[i] * g_cnorm[n * HIDN + i];
        #pragma unroll
        for (int o = 16; o; o >>= 1) p += __shfl_xor_sync(0xffffffffu, p, o);
        if (lane == 0) slog[n] = p;
    }
    __syncthreads();

    if (tid == 0) {
        float sc = inv * 0.0625f * expf(temp[0]);
        float lg[16];
        float mx = -1e30f;
        #pragma unroll
        for (int n = 0; n < NHEAD; n++) {
            lg[n] = slog[n] * sc;
            mx = fmaxf(mx, lg[n]);
        }
        float sum = 0.f;
        #pragma unroll
        for (int n = 0; n < NHEAD; n++) {
            lg[n] = expf(lg[n] - mx);
            sum += lg[n];
        }
        float isum = 1.0f / sum;
        bool used[16];
        #pragma unroll
        for (int n = 0; n < NHEAD; n++) used[n] = false;
        for (int k = 0; k < KSEL; k++) {
            int bi = 0;
            float bv = -1e30f;
            #pragma unroll
            for (int n = 0; n < NHEAD; n++) {
                if (!used[n] && lg[n] > bv) { bv = lg[n]; bi = n; }
            }
            used[bi] = true;
            g_prob[t * KSEL + k] = bv * isum;
            int pos = atomicAdd(&g_cnt[bi], 1);
            g_list[bi * TOK + pos] = (t << 2) | k;
        }
    }
}

// ============================================================
// Kernel 3: grouped expert GEMM, tf32 mma, 2-stage pipelined, BK=16.
// grid (128, 16). Epilogue: out[t, slot*128+n] = (acc + bias) * prob
// ============================================================
__global__ __launch_bounds__(256, 2) void gemm_expert_mma(
    const float* __restrict__ X, const float* __restrict__ W,
    const float* __restrict__ bias, float* __restrict__ out) {
    int h = blockIdx.y;
    int cnt = g_cnt[h];
    int base = blockIdx.x * 128;
    if (base >= cnt) return;

    __shared__ unsigned As[2][128][20];   // 16 k + 4 pad
    __shared__ unsigned Bs[2][128][20];
    __shared__ int   s_ent[128];
    __shared__ float s_prob[128];
    __shared__ float s_bias[128];

    int tid = threadIdx.x;
    if (tid < 128) {
        int r = base + tid;
        int rr = (r < cnt) ? r : (cnt - 1);
        int ent = g_list[h * TOK + rr];
        s_ent[tid] = ent;
        s_prob[tid] = g_prob[ent];
        s_bias[tid] = bias[h * HDIM + tid];
    }
    __syncthreads();

    const float* Wh = W + (size_t)h * HDIM * DIN;
    const float* aptr[2];
    const float* bptr[2];
    int rowL[2], c4L[2];
    #pragma unroll
    for (int i = 0; i < 2; i++) {
        int idx = tid + i * 256;
        rowL[i] = idx >> 2;
        c4L[i] = idx & 3;
        int tok = s_ent[rowL[i]] >> 2;
        aptr[i] = X  + (size_t)tok * DIN + c4L[i] * 4;
        bptr[i] = Wh + (size_t)rowL[i] * DIN + c4L[i] * 4;
    }

    int wid = tid >> 5, lane = tid & 31;
    int wm = wid >> 1, wn = wid & 1;
    int g = lane >> 2, t = lane & 3;

    float acc[2][8][4];
    #pragma unroll
    for (int i = 0; i < 2; i++)
        #pragma unroll
        for (int j = 0; j < 8; j++)
            #pragma unroll
            for (int q = 0; q < 4; q++) acc[i][j][q] = 0.f;

    // prologue: stage 0
    float4 av[2], bv[2];
    #pragma unroll
    for (int i = 0; i < 2; i++) {
        av[i] = *(const float4*)aptr[i];
        bv[i] = *(const float4*)bptr[i];
    }
    #pragma unroll
    for (int i = 0; i < 2; i++) {
        uint4 u;
        u.x = f2tf32(av[i].x); u.y = f2tf32(av[i].y);
        u.z = f2tf32(av[i].z); u.w = f2tf32(av[i].w);
        *(uint4*)&As[0][rowL[i]][c4L[i] * 4] = u;
        u.x = f2tf32(bv[i].x); u.y = f2tf32(bv[i].y);
        u.z = f2tf32(bv[i].z); u.w = f2tf32(bv[i].w);
        *(uint4*)&Bs[0][rowL[i]][c4L[i] * 4] = u;
    }
    __syncthreads();

    int cur = 0;
    for (int k0 = 0; k0 < DIN; k0 += 16) {
        bool nxt = (k0 + 16) < DIN;
        if (nxt) {
            #pragma unroll
            for (int i = 0; i < 2; i++) {
                av[i] = *(const float4*)(aptr[i] + k0 + 16);
                bv[i] = *(const float4*)(bptr[i] + k0 + 16);
            }
        }
        #pragma unroll
        for (int s = 0; s < 2; s++) {
            unsigned a[2][4], b[8][2];
            #pragma unroll
            for (int mt = 0; mt < 2; mt++) {
                int rm = wm * 32 + mt * 16 + g;
                int kc = s * 8 + t;
                a[mt][0] = As[cur][rm][kc];
                a[mt][1] = As[cur][rm + 8][kc];
                a[mt][2] = As[cur][rm][kc + 4];
                a[mt][3] = As[cur][rm + 8][kc + 4];
            }
            #pragma unroll
            for (int nt = 0; nt < 8; nt++) {
                int rn = wn * 64 + nt * 8 + g;
                int kc = s * 8 + t;
                b[nt][0] = Bs[cur][rn][kc];
                b[nt][1] = Bs[cur][rn][kc + 4];
            }
            #pragma unroll
            for (int mt = 0; mt < 2; mt++)
                #pragma unroll
                for (int nt = 0; nt < 8; nt++)
                    mma_tf32(acc[mt][nt], a[mt], b[nt]);
        }
        if (nxt) {
            int st = cur ^ 1;
            #pragma unroll
            for (int i = 0; i < 2; i++) {
                uint4 u;
                u.x = f2tf32(av[i].x); u.y = f2tf32(av[i].y);
                u.z = f2tf32(av[i].z); u.w = f2tf32(av[i].w);
                *(uint4*)&As[st][rowL[i]][c4L[i] * 4] = u;
                u.x = f2tf32(bv[i].x); u.y = f2tf32(bv[i].y);
                u.z = f2tf32(bv[i].z); u.w = f2tf32(bv[i].w);
                *(uint4*)&Bs[st][rowL[i]][c4L[i] * 4] = u;
            }
        }
        __syncthreads();
        cur ^= 1;
    }

    #pragma unroll
    for (int mt = 0; mt < 2; mt++)
        #pragma unroll
        for (int half = 0; half < 2; half++) {
            int r = wm * 32 + mt * 16 + g + half * 8;
            if (base + r < cnt) {
                int ent = s_ent[r];
                int tok = ent >> 2, slot = ent & 3;
                float p = s_prob[r];
                float* op = out + (size_t)tok * OUTW + slot * HDIM;
                #pragma unroll
                for (int nt = 0; nt < 8; nt++) {
                    int col = wn * 64 + nt * 8 + 2 * t;
                    float2 v;
                    v.x = (acc[mt][nt][half * 2 + 0] + s_bias[col]) * p;
                    v.y = (acc[mt][nt][half * 2 + 1] + s_bias[col + 1]) * p;
                    *(float2*)&op[col] = v;
                }
            }
        }
}

// ============================================================
extern "C" void kernel_launch(void* const* d_in, const int* in_sizes, int n_in,
                              void* d_out, int out_size) {
    const float* x    = (const float*)d_in[0];  // [4,4096,2048]
    const float* rw   = (const float*)d_in[1];  // [256,2048]
    const float* cent = (const float*)d_in[2];  // [16,256]
    const float* temp = (const float*)d_in[3];  // [1]
    const float* w    = (const float*)d_in[4];  // [2048,2048]
    const float* b    = (const float*)d_in[5];  // [2048]
    float* out = (float*)d_out;                 // [4,4096,512]

    prep_kernel<<<1, 256>>>(cent);
    gemm_router<<<dim3(HIDN / 128, TOK / 128), 256>>>(x, rw);
    route_kernel<<<TOK, 256>>>(temp);
    gemm_expert_mma<<<dim3(128, 16), 256>>>(x, w, b, out);
}